// round 1
// baseline (speedup 1.0000x reference)
#include <cuda_runtime.h>
#include <cstdint>

// ---------------------------------------------------------------------------
// Problem constants (fixed by the reference's setup_inputs / module constants)
// ---------------------------------------------------------------------------
#define LQ      4096
#define NB      8
#define CDIM    256
#define MROWS   (LQ * NB)          // 32768
#define NHEADS  8
#define NLEV    4
#define NPTS    4
#define DH      32                 // CDIM / NHEADS
#define HLP     (NHEADS * NLEV * NPTS)   // 128

// Spatial pyramid: (100,100),(50,50),(25,25),(13,13); starts 0,10000,12500,13125
// L_total = 13294. feature_maps layout: (L_total, N, C) row-major.

// ---------------------------------------------------------------------------
// Scratch (no cudaMalloc allowed) — ~84 MB of __device__ globals
// ---------------------------------------------------------------------------
__device__ float g_off[MROWS * 256];      // sampling offsets, (row, 256)
__device__ float g_logits[MROWS * 128];   // attn logits pre-softmax, (row, 128)
__device__ float g_agg[MROWS * 256];      // aggregated sampled values, (row, 256)

// ---------------------------------------------------------------------------
// SGEMM: C[M,N] = A[M,K] @ B[K,N] + bias[N]
// BM=BN=128, BK=8, 256 threads, 8x8 per thread. Requires M%128==0, N%128==0,
// K%8==0 (true here: M=32768, N in {256,128}, K=256).
// ---------------------------------------------------------------------------
__global__ __launch_bounds__(256)
void sgemm128(const float* __restrict__ A, const float* __restrict__ B,
              const float* __restrict__ bias, float* __restrict__ Cm,
              int N, int K) {
    __shared__ float As[8][128];
    __shared__ float Bs[8][128];

    const int tid = threadIdx.x;
    const int bx  = blockIdx.x;   // N tile
    const int by  = blockIdx.y;   // M tile

    const float* Ab = A + (size_t)by * 128 * K;
    const float* Bb = B + (size_t)bx * 128;

    const int tx = tid & 15;      // 0..15 -> col group
    const int ty = tid >> 4;      // 0..15 -> row group

    // A tile load mapping: float4 per thread, 2 threads per row
    const int arow = tid >> 1;          // 0..127
    const int acol = (tid & 1) * 4;     // 0 or 4
    // B tile load mapping: float4 per thread, 32 threads per row
    const int brow = tid >> 5;          // 0..7
    const int bcol = (tid & 31) * 4;    // 0..124

    float acc[8][8];
#pragma unroll
    for (int i = 0; i < 8; i++)
#pragma unroll
        for (int j = 0; j < 8; j++) acc[i][j] = 0.f;

    for (int k0 = 0; k0 < K; k0 += 8) {
        float4 a4 = *(const float4*)(Ab + (size_t)arow * K + k0 + acol);
        As[acol + 0][arow] = a4.x;
        As[acol + 1][arow] = a4.y;
        As[acol + 2][arow] = a4.z;
        As[acol + 3][arow] = a4.w;
        float4 b4 = *(const float4*)(Bb + (size_t)(k0 + brow) * N + bcol);
        *(float4*)&Bs[brow][bcol] = b4;
        __syncthreads();

#pragma unroll
        for (int kk = 0; kk < 8; kk++) {
            float4 ra0 = *(const float4*)&As[kk][ty * 8 + 0];
            float4 ra1 = *(const float4*)&As[kk][ty * 8 + 4];
            float4 rb0 = *(const float4*)&Bs[kk][tx * 8 + 0];
            float4 rb1 = *(const float4*)&Bs[kk][tx * 8 + 4];
            float ra[8] = {ra0.x, ra0.y, ra0.z, ra0.w, ra1.x, ra1.y, ra1.z, ra1.w};
            float rb[8] = {rb0.x, rb0.y, rb0.z, rb0.w, rb1.x, rb1.y, rb1.z, rb1.w};
#pragma unroll
            for (int i = 0; i < 8; i++)
#pragma unroll
                for (int j = 0; j < 8; j++) acc[i][j] += ra[i] * rb[j];
        }
        __syncthreads();
    }

#pragma unroll
    for (int i = 0; i < 8; i++) {
        int row = by * 128 + ty * 8 + i;
        float* Crow = Cm + (size_t)row * N + bx * 128 + tx * 8;
#pragma unroll
        for (int j = 0; j < 8; j++)
            Crow[j] = acc[i][j] + bias[bx * 128 + tx * 8 + j];
    }
}

// ---------------------------------------------------------------------------
// Sampling kernel: one block per row r (= lq*8 + n), one warp per head.
// Fuses softmax over the 16 logits per (row, head) + bilinear sampling +
// attn-weighted accumulation. lane = channel within head (dh = 32).
// ---------------------------------------------------------------------------
__global__ __launch_bounds__(256)
void sample_kernel(const float* __restrict__ refpts,
                   const float* __restrict__ fm) {
    const int r    = blockIdx.x;
    const int h    = threadIdx.x >> 5;
    const int lane = threadIdx.x & 31;
    const int n    = r & (NB - 1);
    const int lq   = r >> 3;

    // Per-lane offset value: j = (l*4+p)*2 + xy packed in [h*32, h*32+32)
    const float offv  = g_off[r * 256 + h * 32 + lane];
    // Logit replicated to both warp halves so 16-wide butterfly works cleanly
    const float logit = g_logits[r * 128 + h * 16 + (lane & 15)];

    // Softmax over the 16 (level,point) logits
    float mx = logit;
#pragma unroll
    for (int s = 8; s > 0; s >>= 1)
        mx = fmaxf(mx, __shfl_xor_sync(0xffffffffu, mx, s));
    float ex = __expf(logit - mx);
    float sm = ex;
#pragma unroll
    for (int s = 8; s > 0; s >>= 1)
        sm += __shfl_xor_sync(0xffffffffu, sm, s);
    const float wgt = ex / sm;   // lane holds weight of point (lane & 15)

    const int   Hs[4]     = {100, 50, 25, 13};
    const int   Ws[4]     = {100, 50, 25, 13};
    const int   starts[4] = {0, 10000, 12500, 13125};

    const float* refr = refpts + ((size_t)(n * LQ + lq) * NLEV) * 2;

    float acc = 0.f;
#pragma unroll
    for (int l = 0; l < NLEV; l++) {
        const float rx = refr[l * 2 + 0];
        const float ry = refr[l * 2 + 1];
        const int   Wi = Ws[l], Hi = Hs[l];
        const float Wf = (float)Wi, Hf = (float)Hi;
        const float* base = fm + (size_t)starts[l] * (NB * CDIM)
                               + n * CDIM + h * DH + lane;
#pragma unroll
        for (int p = 0; p < NPTS; p++) {
            const int pt = l * 4 + p;
            const float ox  = __shfl_sync(0xffffffffu, offv, 2 * pt);
            const float oy  = __shfl_sync(0xffffffffu, offv, 2 * pt + 1);
            const float apt = __shfl_sync(0xffffffffu, wgt,  pt);

            // Matches reference: x = loc_x * W - 0.5, loc_x = rx + ox / W
            const float x = (rx + ox / Wf) * Wf - 0.5f;
            const float y = (ry + oy / Hf) * Hf - 0.5f;

            const float x0f = floorf(x), y0f = floorf(y);
            const int   x0 = (int)x0f, y0 = (int)y0f;
            const float wx = x - x0f, wy = y - y0f;

            const bool xv0 = (x0 >= 0)     && (x0 < Wi);
            const bool xv1 = (x0 + 1 >= 0) && (x0 + 1 < Wi);
            const bool yv0 = (y0 >= 0)     && (y0 < Hi);
            const bool yv1 = (y0 + 1 >= 0) && (y0 + 1 < Hi);

            float v00 = 0.f, v01 = 0.f, v10 = 0.f, v11 = 0.f;
            if (yv0) {
                const float* rowp = base + (size_t)y0 * Wi * (NB * CDIM);
                if (xv0) v00 = rowp[(size_t)x0 * (NB * CDIM)];
                if (xv1) v01 = rowp[(size_t)(x0 + 1) * (NB * CDIM)];
            }
            if (yv1) {
                const float* rowp = base + (size_t)(y0 + 1) * Wi * (NB * CDIM);
                if (xv0) v10 = rowp[(size_t)x0 * (NB * CDIM)];
                if (xv1) v11 = rowp[(size_t)(x0 + 1) * (NB * CDIM)];
            }
            const float bil = v00 * (1.f - wx) * (1.f - wy)
                            + v01 * wx         * (1.f - wy)
                            + v10 * (1.f - wx) * wy
                            + v11 * wx         * wy;
            acc += apt * bil;
        }
    }
    g_agg[r * 256 + h * 32 + lane] = acc;
}

// ---------------------------------------------------------------------------
// Launch
// ---------------------------------------------------------------------------
extern "C" void kernel_launch(void* const* d_in, const int* in_sizes, int n_in,
                              void* d_out, int out_size) {
    const float* query   = (const float*)d_in[0];   // (Lq, N, C) == (MROWS, 256)
    const float* refpts  = (const float*)d_in[1];   // (N, Lq, L, 2)
    const float* fmaps   = (const float*)d_in[2];   // (L_total, N, C)
    // d_in[3] = spatial_shapes (compile-time constants here)
    const float* W_off   = (const float*)d_in[4];   // (256, 256)
    const float* b_off   = (const float*)d_in[5];   // (256)
    const float* W_attn  = (const float*)d_in[6];   // (256, 128)
    const float* b_attn  = (const float*)d_in[7];   // (128)
    const float* W_out   = (const float*)d_in[8];   // (256, 256)
    const float* b_out   = (const float*)d_in[9];   // (256)
    float* out = (float*)d_out;                     // (Lq, N, C) == (MROWS, 256)

    float *p_off, *p_logits, *p_agg;
    cudaGetSymbolAddress((void**)&p_off,    g_off);
    cudaGetSymbolAddress((void**)&p_logits, g_logits);
    cudaGetSymbolAddress((void**)&p_agg,    g_agg);

    // GEMM-1a: offsets (N=256)
    sgemm128<<<dim3(2, MROWS / 128), 256>>>(query, W_off,  b_off,  p_off,    256, 256);
    // GEMM-1b: attention logits (N=128)
    sgemm128<<<dim3(1, MROWS / 128), 256>>>(query, W_attn, b_attn, p_logits, 128, 256);
    // Softmax + bilinear sampling + aggregation
    sample_kernel<<<MROWS, 256>>>(refpts, fmaps);
    // GEMM-2: output projection, writes d_out directly
    sgemm128<<<dim3(2, MROWS / 128), 256>>>(p_agg, W_out, b_out, out, 256, 256);
}